// round 9
// baseline (speedup 1.0000x reference)
#include <cuda_runtime.h>
#include <cuda_fp16.h>
#include <cstdint>

// ---------------------------------------------------------------------------
// Problem constants
// ---------------------------------------------------------------------------
#define BW_   2048
#define NTOK  49
#define NH_   12
#define HD_   32
#define DIM_  384
#define M_    (BW_ * NTOK)   // 100352
#define K_    DIM_

// fp16 scratch (device globals; allocation in kernel_launch is forbidden)
__device__ __align__(16) __half g_xh[M_ * DIM_];
__device__ __align__(16) __half g_wh[4 * DIM_ * DIM_];   // qkv_w then proj_w
__device__ __align__(16) __half g_Qh[BW_ * NH_ * NTOK * HD_];
__device__ __align__(16) __half g_Kh[BW_ * NH_ * NTOK * HD_];
__device__ __align__(16) __half g_Vh[BW_ * NH_ * NTOK * HD_];
__device__ __align__(16) __half g_AOh[M_ * DIM_];

// ---------------------------------------------------------------------------
// helpers
// ---------------------------------------------------------------------------
__device__ __forceinline__ uint32_t smem_u32(const void* p) {
    uint32_t a;
    asm("{ .reg .u64 t; cvta.to.shared.u64 t, %1; cvt.u32.u64 %0, t; }"
        : "=r"(a) : "l"(p));
    return a;
}

// 64B-row swizzle (rows of 32 fp16): conflict-free ldsm + 16B stores
__device__ __forceinline__ uint32_t sw_off(int row, int kb) {
    return (uint32_t)(row * 64 + (kb ^ (((row >> 1) & 3) << 4)));
}

// 128B-row swizzle for the transposed-V tile (32 rows x 64 fp16)
__device__ __forceinline__ uint32_t vt_off(int row, int c) {
    return (uint32_t)(row * 128 + ((((c >> 4) ^ (row & 7)) << 4)) + (c & 15));
}

__device__ __forceinline__ void ldsm4(uint32_t* r, uint32_t a) {
    asm volatile("ldmatrix.sync.aligned.m8n8.x4.shared.b16 {%0,%1,%2,%3}, [%4];"
                 : "=r"(r[0]), "=r"(r[1]), "=r"(r[2]), "=r"(r[3]) : "r"(a));
}

__device__ __forceinline__ void mma16816(float* c, const uint32_t* a, const uint32_t* b) {
    asm volatile(
        "mma.sync.aligned.m16n8k16.row.col.f32.f16.f16.f32 "
        "{%0,%1,%2,%3}, {%4,%5,%6,%7}, {%8,%9}, {%0,%1,%2,%3};"
        : "+f"(c[0]), "+f"(c[1]), "+f"(c[2]), "+f"(c[3])
        : "r"(a[0]), "r"(a[1]), "r"(a[2]), "r"(a[3]), "r"(b[0]), "r"(b[1]));
}

__device__ __forceinline__ void cp16(uint32_t dst, const void* src) {
    asm volatile("cp.async.cg.shared.global [%0], [%1], 16;" :: "r"(dst), "l"(src));
}
#define CP_COMMIT() asm volatile("cp.async.commit_group;")
#define CP_WAIT(n)  asm volatile("cp.async.wait_group %0;" :: "n"(n))

__device__ __forceinline__ uint32_t h2u(__half2 h) { return *(uint32_t*)&h; }

// ---------------------------------------------------------------------------
// fp32 -> fp16 convert, all three tensors in one launch
// ---------------------------------------------------------------------------
#define N4X ((M_ * DIM_) / 4)
#define N4W ((3 * DIM_ * DIM_) / 4)
#define N4P ((DIM_ * DIM_) / 4)

__global__ void cvt_all(const float4* __restrict__ x,
                        const float4* __restrict__ qw,
                        const float4* __restrict__ pw) {
    int i = blockIdx.x * blockDim.x + threadIdx.x;
    const float4* src;
    __half* dst;
    int j;
    if (i < N4X)                 { src = x;  dst = g_xh;                   j = i; }
    else if (i < N4X + N4W)      { src = qw; dst = g_wh;                   j = i - N4X; }
    else if (i < N4X + N4W + N4P){ src = pw; dst = g_wh + 3 * DIM_ * DIM_; j = i - N4X - N4W; }
    else return;
    float4 f = src[j];
    uint2 u;
    u.x = h2u(__floats2half2_rn(f.x, f.y));
    u.y = h2u(__floats2half2_rn(f.z, f.w));
    *(uint2*)(dst + (size_t)j * 4) = u;
}

// ---------------------------------------------------------------------------
// fp16 GEMM (f32 acc): C[M,N] = A[M,K] * B[N,K]^T (+bias)
// MODE 0: A = g_xh, B = qkv weights, N=1152, epilogue -> fp16 Q/K/V scatter
// MODE 1: A = g_AOh, B = proj weights, N=384, epilogue -> fp32 out
// CTA 128x64x32, 8 warps (4m x 2n), warp tile 32x32, 3-stage cp.async,
// 3 CTAs/SM (24 warps) for latency hiding. KT fully unrolled.
// ---------------------------------------------------------------------------
#define BM 128
#define BN 64
#define BK 32
#define KT (K_ / BK)   // 12

template <int MODE>
__global__ __launch_bounds__(256, 3)
void gemm_h(const float* __restrict__ bias, float* __restrict__ out) {
    __shared__ __align__(16) __half sA[3][BM * BK];   // 8 KB / stage
    __shared__ __align__(16) __half sB[3][BN * BK];   // 4 KB / stage

    const __half* Ah = (MODE == 0) ? g_xh : g_AOh;
    const __half* Bh = (MODE == 0) ? g_wh : g_wh + 3 * DIM_ * DIM_;

    const int tid  = threadIdx.x;
    const int lane = tid & 31;
    const int wid  = tid >> 5;
    const int wm   = wid & 3;     // m: 4 warps x 32
    const int wn   = wid >> 2;    // n: 2 warps x 32
    const int bm   = blockIdx.y * BM;
    const int bn   = blockIdx.x * BN;

    // loader: row = tid>>2 (A also +64), 16B chunk col = tid&3
    const int lrow = tid >> 2;
    const int lc   = tid & 3;
    const __half* Asrc = Ah + (size_t)(bm + lrow) * K_ + lc * 8;
    const __half* Bsrc = Bh + (size_t)(bn + lrow) * K_ + lc * 8;
    const uint32_t sw0 = sw_off(lrow, lc * 16);
    const uint32_t sw1 = sw_off(lrow + 64, lc * 16);

    uint32_t aSb[3], bSb[3];
#pragma unroll
    for (int s = 0; s < 3; ++s) { aSb[s] = smem_u32(sA[s]); bSb[s] = smem_u32(sB[s]); }

    // fragment offsets (k-slice ks -> ^ (ks<<5))
    const int arow = wm * 32 + (lane & 15);
    const uint32_t akb = ((lane >> 4) & 1) * 16;
    const uint32_t aoff0 = sw_off(arow, akb);
    const uint32_t aoff1 = sw_off(arow + 16, akb);
    const int nrB = (lane & 7) + ((lane >> 4) & 1) * 8;
    const uint32_t bkb = ((lane >> 3) & 1) * 16;
    const uint32_t boff0 = sw_off(wn * 32 + nrB, bkb);
    const uint32_t boff1 = sw_off(wn * 32 + 16 + nrB, bkb);

    float acc[2][4][4];
#pragma unroll
    for (int mf = 0; mf < 2; ++mf)
#pragma unroll
        for (int f = 0; f < 4; ++f)
#pragma unroll
            for (int e = 0; e < 4; ++e) acc[mf][f][e] = 0.f;

    auto issue = [&](int kt) {
        const int st = kt % 3;
        const __half* as = Asrc + kt * BK;
        cp16(aSb[st] + sw0, as);
        cp16(aSb[st] + sw1, as + (size_t)64 * K_);
        cp16(bSb[st] + sw0, Bsrc + kt * BK);
        CP_COMMIT();
    };

    issue(0);
    issue(1);

#pragma unroll
    for (int kt = 0; kt < KT; ++kt) {
        if (kt + 1 < KT) { CP_WAIT(1); } else { CP_WAIT(0); }
        __syncthreads();
        if (kt + 2 < KT) issue(kt + 2);

        const uint32_t aB = aSb[kt % 3], bB = bSb[kt % 3];
#pragma unroll
        for (int ks = 0; ks < 2; ++ks) {
            const uint32_t kx = (uint32_t)ks << 5;
            uint32_t af0[4], af1[4], bf0[4], bf1[4];
            ldsm4(af0, aB + (aoff0 ^ kx));
            ldsm4(af1, aB + (aoff1 ^ kx));
            ldsm4(bf0, bB + (boff0 ^ kx));
            ldsm4(bf1, bB + (boff1 ^ kx));
            mma16816(acc[0][0], af0, bf0);
            mma16816(acc[0][1], af0, bf0 + 2);
            mma16816(acc[0][2], af0, bf1);
            mma16816(acc[0][3], af0, bf1 + 2);
            mma16816(acc[1][0], af1, bf0);
            mma16816(acc[1][1], af1, bf0 + 2);
            mma16816(acc[1][2], af1, bf1);
            mma16816(acc[1][3], af1, bf1 + 2);
        }
    }

    // ---- epilogue ----
    const int gr = lane >> 2, tg = lane & 3;
    const int n0 = bn + wn * 32;

    if (MODE == 0) {
        const int which = n0 / DIM_;            // n0 is 32-aligned, head-uniform
        const int hh    = (n0 - which * DIM_) >> 5;
        const float scl = (which == 0) ? 0.17677669529663687f : 1.0f;
        __half* dst = (which == 0) ? g_Qh : (which == 1) ? g_Kh : g_Vh;
#pragma unroll
        for (int mf = 0; mf < 2; ++mf) {
#pragma unroll
            for (int e = 0; e < 2; ++e) {
                const int row = bm + wm * 32 + mf * 16 + gr + e * 8;
                const int bwin = row / NTOK;
                const int t = row - bwin * NTOK;
                __half* o = dst + ((size_t)(bwin * NH_ + hh) * NTOK + t) * HD_;
#pragma unroll
                for (int f = 0; f < 4; ++f) {
                    const int cl = f * 8 + tg * 2;
                    float v0 = (acc[mf][f][e * 2 + 0] + bias[n0 + cl + 0]) * scl;
                    float v1 = (acc[mf][f][e * 2 + 1] + bias[n0 + cl + 1]) * scl;
                    *(__half2*)(o + cl) = __floats2half2_rn(v0, v1);
                }
            }
        }
    } else {
#pragma unroll
        for (int mf = 0; mf < 2; ++mf) {
#pragma unroll
            for (int e = 0; e < 2; ++e) {
                const int row = bm + wm * 32 + mf * 16 + gr + e * 8;
#pragma unroll
                for (int f = 0; f < 4; ++f) {
                    const int n = n0 + f * 8 + tg * 2;
                    float2 w;
                    w.x = acc[mf][f][e * 2 + 0] + bias[n + 0];
                    w.y = acc[mf][f][e * 2 + 1] + bias[n + 1];
                    *(float2*)(out + (size_t)row * DIM_ + n) = w;
                }
            }
        }
    }
}

// ---------------------------------------------------------------------------
// Tensorized window attention: one CTA (128 thr / 4 warps) per 4 (window,head)
// pairs, processed sequentially (16 CTAs/SM overlap across the sequence).
// ---------------------------------------------------------------------------
#define PAIRS_PER_CTA 4

__global__ __launch_bounds__(128)
void attn_tc(const float* __restrict__ table) {
    __shared__ __align__(16) __half sQ[64 * 32];
    __shared__ __align__(16) __half sK[64 * 32];
    __shared__ __align__(16) __half sVT[32 * 64];
    __shared__ float sbias[169];

    const int tid  = threadIdx.x;
    const int lane = tid & 31;
    const int w    = tid >> 5;
    const uint32_t sQb = smem_u32(sQ), sKb = smem_u32(sK), sVb = smem_u32(sVT);
    const int gr = lane >> 2, tg = lane & 3;

    for (int pp = 0; pp < PAIRS_PER_CTA; ++pp) {
        const int pair = blockIdx.x * PAIRS_PER_CTA + pp;
        const int bw = pair / NH_;
        const int h  = pair % NH_;

        const __half* qg = g_Qh + (size_t)pair * NTOK * HD_;
        const __half* kg = g_Kh + (size_t)pair * NTOK * HD_;
        const __half* vg = g_Vh + (size_t)pair * NTOK * HD_;

        if (pp) __syncthreads();   // prev compute done before smem overwrite

        // zero V^T pad columns (tokens 48..63)
        if (tid < 64) {
            const int r = tid >> 1, c = (6 + (tid & 1)) * 16;
            *(uint4*)((char*)sVT + vt_off(r, c)) = make_uint4(0, 0, 0, 0);
        }
        for (int i = tid; i < 196; i += 128) {
            const int r = i >> 2, c = (i & 3) * 16;
            uint4 q4 = *(const uint4*)(qg + r * HD_ + (i & 3) * 8);
            uint4 k4 = *(const uint4*)(kg + r * HD_ + (i & 3) * 8);
            *(uint4*)((char*)sQ + sw_off(r, c)) = q4;
            *(uint4*)((char*)sK + sw_off(r, c)) = k4;
        }
        for (int i = tid; i < 169; i += 128) sbias[i] = table[i * NH_ + h];
        for (int i = tid; i < 196; i += 128) {
            const int tok = i >> 2, d0 = (i & 3) * 8;
            uint4 v4 = *(const uint4*)(vg + tok * HD_ + d0);
            __half hv[8];
            *(uint4*)hv = v4;
#pragma unroll
            for (int j = 0; j < 8; ++j)
                *(__half*)((char*)sVT + vt_off(d0 + j, tok * 2)) = hv[j];
        }
        __syncthreads();

        // S = Q K^T
        float sacc[8][4];
#pragma unroll
        for (int f = 0; f < 8; ++f)
#pragma unroll
            for (int e = 0; e < 4; ++e) sacc[f][e] = 0.f;

        const uint32_t aoff = sw_off(w * 16 + (lane & 15), ((lane >> 4) & 1) * 16);
        const int nrB = (lane & 7) + ((lane >> 4) & 1) * 8;
        const uint32_t bkb = ((lane >> 3) & 1) * 16;
#pragma unroll
        for (int ks = 0; ks < 2; ++ks) {
            const uint32_t kx = ks * 32;
            uint32_t af[4];
            ldsm4(af, sQb + (aoff ^ kx));
#pragma unroll
            for (int p = 0; p < 4; ++p) {
                uint32_t bf[4];
                ldsm4(bf, sKb + (sw_off(p * 16 + nrB, bkb) ^ kx));
                mma16816(sacc[2 * p],     af, bf);
                mma16816(sacc[2 * p + 1], af, bf + 2);
            }
        }

        // bias + mask + softmax
        const int r0 = w * 16 + gr, r1 = r0 + 8;
        const int r0d = r0 / 7, r0m = r0 - r0d * 7;
        const int r1d = r1 / 7, r1m = r1 - r1d * 7;
        float mx0 = -1e30f, mx1 = -1e30f;
#pragma unroll
        for (int f = 0; f < 8; ++f) {
#pragma unroll
            for (int c = 0; c < 2; ++c) {
                const int j = f * 8 + tg * 2 + c;
                const int jd = j / 7, jm = j - jd * 7;
                const bool jv = (j < NTOK);
                float s0 = -1e30f, s1 = -1e30f;
                if (jv) {
                    float b0 = (r0 < NTOK) ? sbias[(r0d - jd + 6) * 13 + (r0m - jm + 6)] : 0.f;
                    float b1 = (r1 < NTOK) ? sbias[(r1d - jd + 6) * 13 + (r1m - jm + 6)] : 0.f;
                    s0 = sacc[f][c]     + b0;
                    s1 = sacc[f][c + 2] + b1;
                }
                sacc[f][c]     = s0;
                sacc[f][c + 2] = s1;
                mx0 = fmaxf(mx0, s0);
                mx1 = fmaxf(mx1, s1);
            }
        }
        mx0 = fmaxf(mx0, __shfl_xor_sync(0xffffffffu, mx0, 1));
        mx0 = fmaxf(mx0, __shfl_xor_sync(0xffffffffu, mx0, 2));
        mx1 = fmaxf(mx1, __shfl_xor_sync(0xffffffffu, mx1, 1));
        mx1 = fmaxf(mx1, __shfl_xor_sync(0xffffffffu, mx1, 2));

        float sum0 = 0.f, sum1 = 0.f;
#pragma unroll
        for (int f = 0; f < 8; ++f) {
            float e0 = __expf(sacc[f][0] - mx0);
            float e1 = __expf(sacc[f][1] - mx0);
            float e2 = __expf(sacc[f][2] - mx1);
            float e3 = __expf(sacc[f][3] - mx1);
            sacc[f][0] = e0; sacc[f][1] = e1; sacc[f][2] = e2; sacc[f][3] = e3;
            sum0 += e0 + e1;
            sum1 += e2 + e3;
        }
        sum0 += __shfl_xor_sync(0xffffffffu, sum0, 1);
        sum0 += __shfl_xor_sync(0xffffffffu, sum0, 2);
        sum1 += __shfl_xor_sync(0xffffffffu, sum1, 1);
        sum1 += __shfl_xor_sync(0xffffffffu, sum1, 2);
        const float inv0 = __frcp_rn(sum0);
        const float inv1 = __frcp_rn(sum1);

        // P -> A fragments
        uint32_t pa[4][4];
#pragma unroll
        for (int ks = 0; ks < 4; ++ks) {
            pa[ks][0] = h2u(__floats2half2_rn(sacc[2 * ks][0],     sacc[2 * ks][1]));
            pa[ks][1] = h2u(__floats2half2_rn(sacc[2 * ks][2],     sacc[2 * ks][3]));
            pa[ks][2] = h2u(__floats2half2_rn(sacc[2 * ks + 1][0], sacc[2 * ks + 1][1]));
            pa[ks][3] = h2u(__floats2half2_rn(sacc[2 * ks + 1][2], sacc[2 * ks + 1][3]));
        }

        // O = P V
        float oacc[4][4];
#pragma unroll
        for (int f = 0; f < 4; ++f)
#pragma unroll
            for (int e = 0; e < 4; ++e) oacc[f][e] = 0.f;

#pragma unroll
        for (int ks = 0; ks < 4; ++ks) {
            const int kbv = ks * 32 + ((lane >> 3) & 1) * 16;
#pragma unroll
            for (int p = 0; p < 2; ++p) {
                uint32_t bf[4];
                ldsm4(bf, sVb + vt_off(p * 16 + nrB, kbv));
                mma16816(oacc[2 * p],     pa[ks], bf);
                mma16816(oacc[2 * p + 1], pa[ks], bf + 2);
            }
        }

        if (r0 < NTOK) {
            __half* o = g_AOh + ((size_t)bw * NTOK + r0) * DIM_ + h * HD_;
#pragma unroll
            for (int f = 0; f < 4; ++f) {
                const int d = f * 8 + tg * 2;
                *(__half2*)(o + d) =
                    __floats2half2_rn(oacc[f][0] * inv0, oacc[f][1] * inv0);
            }
        }
        if (r1 < NTOK) {
            __half* o = g_AOh + ((size_t)bw * NTOK + r1) * DIM_ + h * HD_;
#pragma unroll
            for (int f = 0; f < 4; ++f) {
                const int d = f * 8 + tg * 2;
                *(__half2*)(o + d) =
                    __floats2half2_rn(oacc[f][2] * inv1, oacc[f][3] * inv1);
            }
        }
    }
}

// ---------------------------------------------------------------------------
extern "C" void kernel_launch(void* const* d_in, const int* in_sizes, int n_in,
                              void* d_out, int out_size) {
    const float* x      = (const float*)d_in[0];
    const float* qkv_w  = (const float*)d_in[1];
    const float* qkv_b  = (const float*)d_in[2];
    const float* proj_w = (const float*)d_in[3];
    const float* proj_b = (const float*)d_in[4];
    const float* table  = (const float*)d_in[5];
    float* out = (float*)d_out;

    const int n4 = N4X + N4W + N4P;
    cvt_all<<<(n4 + 255) / 256, 256>>>((const float4*)x, (const float4*)qkv_w,
                                       (const float4*)proj_w);

    gemm_h<0><<<dim3((3 * DIM_) / BN, M_ / BM), 256>>>(qkv_b, nullptr);

    attn_tc<<<(BW_ * NH_) / PAIRS_PER_CTA, 128>>>(table);

    gemm_h<1><<<dim3(DIM_ / BN, M_ / BM), 256>>>(proj_b, out);
}

// round 10
// speedup vs baseline: 1.1612x; 1.1612x over previous
#include <cuda_runtime.h>
#include <cuda_fp16.h>
#include <cstdint>

// ---------------------------------------------------------------------------
// Problem constants
// ---------------------------------------------------------------------------
#define BW_   2048
#define NTOK  49
#define NH_   12
#define HD_   32
#define DIM_  384
#define M_    (BW_ * NTOK)   // 100352
#define K_    DIM_

// fp16 scratch (device globals; allocation in kernel_launch is forbidden)
__device__ __align__(16) __half g_xh[M_ * DIM_];
__device__ __align__(16) __half g_wh[4 * DIM_ * DIM_];   // qkv_w then proj_w
__device__ __align__(16) __half g_Qh[BW_ * NH_ * NTOK * HD_];
__device__ __align__(16) __half g_Kh[BW_ * NH_ * NTOK * HD_];
__device__ __align__(16) __half g_Vh[BW_ * NH_ * NTOK * HD_];
__device__ __align__(16) __half g_AOh[M_ * DIM_];

// ---------------------------------------------------------------------------
// helpers
// ---------------------------------------------------------------------------
__device__ __forceinline__ uint32_t smem_u32(const void* p) {
    uint32_t a;
    asm("{ .reg .u64 t; cvta.to.shared.u64 t, %1; cvt.u32.u64 %0, t; }"
        : "=r"(a) : "l"(p));
    return a;
}

// 64B-row swizzle (rows of 32 fp16): conflict-free ldsm + 16B stores
__device__ __forceinline__ uint32_t sw_off(int row, int kb) {
    return (uint32_t)(row * 64 + (kb ^ (((row >> 1) & 3) << 4)));
}

// 128B-row swizzle for the transposed-V tile (32 rows x 64 fp16)
__device__ __forceinline__ uint32_t vt_off(int row, int c) {
    return (uint32_t)(row * 128 + ((((c >> 4) ^ (row & 7)) << 4)) + (c & 15));
}

__device__ __forceinline__ void ldsm4(uint32_t* r, uint32_t a) {
    asm volatile("ldmatrix.sync.aligned.m8n8.x4.shared.b16 {%0,%1,%2,%3}, [%4];"
                 : "=r"(r[0]), "=r"(r[1]), "=r"(r[2]), "=r"(r[3]) : "r"(a));
}

__device__ __forceinline__ void mma16816(float* c, const uint32_t* a, const uint32_t* b) {
    asm volatile(
        "mma.sync.aligned.m16n8k16.row.col.f32.f16.f16.f32 "
        "{%0,%1,%2,%3}, {%4,%5,%6,%7}, {%8,%9}, {%0,%1,%2,%3};"
        : "+f"(c[0]), "+f"(c[1]), "+f"(c[2]), "+f"(c[3])
        : "r"(a[0]), "r"(a[1]), "r"(a[2]), "r"(a[3]), "r"(b[0]), "r"(b[1]));
}

__device__ __forceinline__ void cp16(uint32_t dst, const void* src) {
    asm volatile("cp.async.cg.shared.global [%0], [%1], 16;" :: "r"(dst), "l"(src));
}
#define CP_COMMIT() asm volatile("cp.async.commit_group;")
#define CP_WAIT(n)  asm volatile("cp.async.wait_group %0;" :: "n"(n))

__device__ __forceinline__ uint32_t h2u(__half2 h) { return *(uint32_t*)&h; }

// ---------------------------------------------------------------------------
// fp32 -> fp16 convert, all three tensors in one launch
// ---------------------------------------------------------------------------
#define N4X ((M_ * DIM_) / 4)
#define N4W ((3 * DIM_ * DIM_) / 4)
#define N4P ((DIM_ * DIM_) / 4)

__global__ void cvt_all(const float4* __restrict__ x,
                        const float4* __restrict__ qw,
                        const float4* __restrict__ pw) {
    int i = blockIdx.x * blockDim.x + threadIdx.x;
    const float4* src;
    __half* dst;
    int j;
    if (i < N4X)                 { src = x;  dst = g_xh;                   j = i; }
    else if (i < N4X + N4W)      { src = qw; dst = g_wh;                   j = i - N4X; }
    else if (i < N4X + N4W + N4P){ src = pw; dst = g_wh + 3 * DIM_ * DIM_; j = i - N4X - N4W; }
    else return;
    float4 f = src[j];
    uint2 u;
    u.x = h2u(__floats2half2_rn(f.x, f.y));
    u.y = h2u(__floats2half2_rn(f.z, f.w));
    *(uint2*)(dst + (size_t)j * 4) = u;
}

// ---------------------------------------------------------------------------
// fp16 GEMM (f32 acc): C[M,N] = A[M,K] * B[N,K]^T (+bias)
// MODE 0: A = g_xh, B = qkv weights, N=1152, epilogue -> fp16 Q/K/V scatter
// MODE 1: A = g_AOh, B = proj weights, N=384, epilogue -> fp32 out
// CTA 128x128x32, 8 warps (4m x 2n), warp tile 32x64, 5-stage cp.async
// (3 chunks in flight), 2 CTAs/SM.
// ---------------------------------------------------------------------------
#define BM 128
#define BN 128
#define BK 32
#define KT (K_ / BK)            // 12
#define STAGES 5
#define A_ST (BM * BK * 2)      // 8192 B
#define B_ST (BN * BK * 2)      // 8192 B
#define STG_ (A_ST + B_ST)      // 16384 B
#define GSMEM (STAGES * STG_)   // 81920 B

template <int MODE>
__global__ __launch_bounds__(256, 2)
void gemm_h(const float* __restrict__ bias, float* __restrict__ out) {
    extern __shared__ __align__(16) uint8_t smem[];

    const __half* Ah = (MODE == 0) ? g_xh : g_AOh;
    const __half* Bh = (MODE == 0) ? g_wh : g_wh + 3 * DIM_ * DIM_;

    const int tid  = threadIdx.x;
    const int lane = tid & 31;
    const int wid  = tid >> 5;
    const int wm   = wid & 3;
    const int wn   = wid >> 2;
    const int bm   = blockIdx.y * BM;
    const int bn   = blockIdx.x * BN;

    // loader: row = tid>>2 (+64), 16B chunk col = tid&3
    const int lrow = tid >> 2;
    const int lc   = tid & 3;
    const __half* Asrc = Ah + (size_t)(bm + lrow) * K_ + lc * 8;
    const __half* Bsrc = Bh + (size_t)(bn + lrow) * K_ + lc * 8;
    const uint32_t sw0 = sw_off(lrow, lc * 16);
    const uint32_t sw1 = sw_off(lrow + 64, lc * 16);

    const uint32_t sb = smem_u32(smem);

    // fragment offsets (k-slice ks -> ^ (ks<<5))
    const int arow = wm * 32 + (lane & 15);
    const uint32_t akb = ((lane >> 4) & 1) * 16;
    const uint32_t aoff0 = sw_off(arow, akb);
    const uint32_t aoff1 = sw_off(arow + 16, akb);
    const int nrB = (lane & 7) + ((lane >> 4) & 1) * 8;
    const uint32_t bkb = ((lane >> 3) & 1) * 16;
    uint32_t boff[4];
#pragma unroll
    for (int p = 0; p < 4; ++p) boff[p] = sw_off(wn * 64 + p * 16 + nrB, bkb);

    float acc[2][8][4];
#pragma unroll
    for (int mf = 0; mf < 2; ++mf)
#pragma unroll
        for (int f = 0; f < 8; ++f)
#pragma unroll
            for (int e = 0; e < 4; ++e) acc[mf][f][e] = 0.f;

    auto issue = [&](int kt) {
        const uint32_t ab = sb + (kt % STAGES) * STG_;
        const uint32_t bb = ab + A_ST;
        const __half* as = Asrc + kt * BK;
        const __half* bs = Bsrc + kt * BK;
        cp16(ab + sw0, as);
        cp16(ab + sw1, as + (size_t)64 * K_);
        cp16(bb + sw0, bs);
        cp16(bb + sw1, bs + (size_t)64 * K_);
        CP_COMMIT();
    };

    issue(0); issue(1); issue(2); issue(3);

#pragma unroll
    for (int kt = 0; kt < KT; ++kt) {
        if (kt < KT - 3)      { CP_WAIT(3); }
        else if (kt == KT - 3){ CP_WAIT(2); }
        else if (kt == KT - 2){ CP_WAIT(1); }
        else                  { CP_WAIT(0); }
        __syncthreads();
        if (kt + 4 < KT) issue(kt + 4);

        const uint32_t aB = sb + (kt % STAGES) * STG_;
        const uint32_t bB = aB + A_ST;
#pragma unroll
        for (int ks = 0; ks < 2; ++ks) {
            const uint32_t kx = (uint32_t)ks << 5;
            uint32_t af0[4], af1[4];
            ldsm4(af0, aB + (aoff0 ^ kx));
            ldsm4(af1, aB + (aoff1 ^ kx));
#pragma unroll
            for (int p = 0; p < 4; ++p) {
                uint32_t bf[4];
                ldsm4(bf, bB + (boff[p] ^ kx));
                mma16816(acc[0][2 * p],     af0, bf);
                mma16816(acc[0][2 * p + 1], af0, bf + 2);
                mma16816(acc[1][2 * p],     af1, bf);
                mma16816(acc[1][2 * p + 1], af1, bf + 2);
            }
        }
    }

    // ---- epilogue ----
    const int gr = lane >> 2, tg = lane & 3;

    if (MODE == 0) {
        const int which = bn / DIM_;
        const float scl = (which == 0) ? 0.17677669529663687f : 1.0f;
        __half* dst = (which == 0) ? g_Qh : (which == 1) ? g_Kh : g_Vh;
#pragma unroll
        for (int mf = 0; mf < 2; ++mf) {
#pragma unroll
            for (int e = 0; e < 2; ++e) {
                const int row = bm + wm * 32 + mf * 16 + gr + e * 8;
                const int bwin = row / NTOK;
                const int t = row - bwin * NTOK;
#pragma unroll
                for (int f = 0; f < 8; ++f) {
                    const int n = bn + wn * 64 + f * 8 + tg * 2;
                    const int hh = (n - which * DIM_) >> 5;
                    const int cl = n & 31;
                    float v0 = (acc[mf][f][e * 2 + 0] + bias[n + 0]) * scl;
                    float v1 = (acc[mf][f][e * 2 + 1] + bias[n + 1]) * scl;
                    *(__half2*)(dst + ((size_t)(bwin * NH_ + hh) * NTOK + t) * HD_ + cl) =
                        __floats2half2_rn(v0, v1);
                }
            }
        }
    } else {
#pragma unroll
        for (int mf = 0; mf < 2; ++mf) {
#pragma unroll
            for (int e = 0; e < 2; ++e) {
                const int row = bm + wm * 32 + mf * 16 + gr + e * 8;
#pragma unroll
                for (int f = 0; f < 8; ++f) {
                    const int n = bn + wn * 64 + f * 8 + tg * 2;
                    float2 w;
                    w.x = acc[mf][f][e * 2 + 0] + bias[n + 0];
                    w.y = acc[mf][f][e * 2 + 1] + bias[n + 1];
                    *(float2*)(out + (size_t)row * DIM_ + n) = w;
                }
            }
        }
    }
}

// ---------------------------------------------------------------------------
// Tensorized window attention: one CTA (128 thr / 4 warps) per (window, head)
// ---------------------------------------------------------------------------
__global__ __launch_bounds__(128)
void attn_tc(const float* __restrict__ table) {
    __shared__ __align__(16) __half sQ[64 * 32];
    __shared__ __align__(16) __half sK[64 * 32];
    __shared__ __align__(16) __half sVT[32 * 64];
    __shared__ float sbias[169];

    const int tid  = threadIdx.x;
    const int lane = tid & 31;
    const int w    = tid >> 5;
    const int bw   = blockIdx.x / NH_;
    const int h    = blockIdx.x % NH_;

    const __half* qg = g_Qh + (size_t)blockIdx.x * NTOK * HD_;
    const __half* kg = g_Kh + (size_t)blockIdx.x * NTOK * HD_;
    const __half* vg = g_Vh + (size_t)blockIdx.x * NTOK * HD_;
    const uint32_t sQb = smem_u32(sQ), sKb = smem_u32(sK), sVb = smem_u32(sVT);

    // zero V^T pad columns (tokens 48..63)
    if (tid < 64) {
        const int r = tid >> 1, c = (6 + (tid & 1)) * 16;
        *(uint4*)((char*)sVT + vt_off(r, c)) = make_uint4(0, 0, 0, 0);
    }
    for (int i = tid; i < 196; i += 128) {
        const int r = i >> 2, c = (i & 3) * 16;
        uint4 q4 = *(const uint4*)(qg + r * HD_ + (i & 3) * 8);
        uint4 k4 = *(const uint4*)(kg + r * HD_ + (i & 3) * 8);
        *(uint4*)((char*)sQ + sw_off(r, c)) = q4;
        *(uint4*)((char*)sK + sw_off(r, c)) = k4;
    }
    for (int i = tid; i < 169; i += 128) sbias[i] = table[i * NH_ + h];
    for (int i = tid; i < 196; i += 128) {
        const int tok = i >> 2, d0 = (i & 3) * 8;
        uint4 v4 = *(const uint4*)(vg + tok * HD_ + d0);
        __half hv[8];
        *(uint4*)hv = v4;
#pragma unroll
        for (int j = 0; j < 8; ++j)
            *(__half*)((char*)sVT + vt_off(d0 + j, tok * 2)) = hv[j];
    }
    __syncthreads();

    const int gr = lane >> 2, tg = lane & 3;

    // S = Q K^T
    float sacc[8][4];
#pragma unroll
    for (int f = 0; f < 8; ++f)
#pragma unroll
        for (int e = 0; e < 4; ++e) sacc[f][e] = 0.f;

    const uint32_t aoff = sw_off(w * 16 + (lane & 15), ((lane >> 4) & 1) * 16);
    const int nrB = (lane & 7) + ((lane >> 4) & 1) * 8;
    const uint32_t bkb = ((lane >> 3) & 1) * 16;
#pragma unroll
    for (int ks = 0; ks < 2; ++ks) {
        const uint32_t kx = ks * 32;
        uint32_t af[4];
        ldsm4(af, sQb + (aoff ^ kx));
#pragma unroll
        for (int p = 0; p < 4; ++p) {
            uint32_t bf[4];
            ldsm4(bf, sKb + (sw_off(p * 16 + nrB, bkb) ^ kx));
            mma16816(sacc[2 * p],     af, bf);
            mma16816(sacc[2 * p + 1], af, bf + 2);
        }
    }

    // bias + mask + softmax
    const int r0 = w * 16 + gr, r1 = r0 + 8;
    const int r0d = r0 / 7, r0m = r0 - r0d * 7;
    const int r1d = r1 / 7, r1m = r1 - r1d * 7;
    float mx0 = -1e30f, mx1 = -1e30f;
#pragma unroll
    for (int f = 0; f < 8; ++f) {
#pragma unroll
        for (int c = 0; c < 2; ++c) {
            const int j = f * 8 + tg * 2 + c;
            const int jd = j / 7, jm = j - jd * 7;
            const bool jv = (j < NTOK);
            float s0 = -1e30f, s1 = -1e30f;
            if (jv) {
                float b0 = (r0 < NTOK) ? sbias[(r0d - jd + 6) * 13 + (r0m - jm + 6)] : 0.f;
                float b1 = (r1 < NTOK) ? sbias[(r1d - jd + 6) * 13 + (r1m - jm + 6)] : 0.f;
                s0 = sacc[f][c]     + b0;
                s1 = sacc[f][c + 2] + b1;
            }
            sacc[f][c]     = s0;
            sacc[f][c + 2] = s1;
            mx0 = fmaxf(mx0, s0);
            mx1 = fmaxf(mx1, s1);
        }
    }
    mx0 = fmaxf(mx0, __shfl_xor_sync(0xffffffffu, mx0, 1));
    mx0 = fmaxf(mx0, __shfl_xor_sync(0xffffffffu, mx0, 2));
    mx1 = fmaxf(mx1, __shfl_xor_sync(0xffffffffu, mx1, 1));
    mx1 = fmaxf(mx1, __shfl_xor_sync(0xffffffffu, mx1, 2));

    float sum0 = 0.f, sum1 = 0.f;
#pragma unroll
    for (int f = 0; f < 8; ++f) {
        float e0 = __expf(sacc[f][0] - mx0);
        float e1 = __expf(sacc[f][1] - mx0);
        float e2 = __expf(sacc[f][2] - mx1);
        float e3 = __expf(sacc[f][3] - mx1);
        sacc[f][0] = e0; sacc[f][1] = e1; sacc[f][2] = e2; sacc[f][3] = e3;
        sum0 += e0 + e1;
        sum1 += e2 + e3;
    }
    sum0 += __shfl_xor_sync(0xffffffffu, sum0, 1);
    sum0 += __shfl_xor_sync(0xffffffffu, sum0, 2);
    sum1 += __shfl_xor_sync(0xffffffffu, sum1, 1);
    sum1 += __shfl_xor_sync(0xffffffffu, sum1, 2);
    const float inv0 = __frcp_rn(sum0);
    const float inv1 = __frcp_rn(sum1);

    // P -> A fragments
    uint32_t pa[4][4];
#pragma unroll
    for (int ks = 0; ks < 4; ++ks) {
        pa[ks][0] = h2u(__floats2half2_rn(sacc[2 * ks][0],     sacc[2 * ks][1]));
        pa[ks][1] = h2u(__floats2half2_rn(sacc[2 * ks][2],     sacc[2 * ks][3]));
        pa[ks][2] = h2u(__floats2half2_rn(sacc[2 * ks + 1][0], sacc[2 * ks + 1][1]));
        pa[ks][3] = h2u(__floats2half2_rn(sacc[2 * ks + 1][2], sacc[2 * ks + 1][3]));
    }

    // O = P V
    float oacc[4][4];
#pragma unroll
    for (int f = 0; f < 4; ++f)
#pragma unroll
        for (int e = 0; e < 4; ++e) oacc[f][e] = 0.f;

#pragma unroll
    for (int ks = 0; ks < 4; ++ks) {
        const int kbv = ks * 32 + ((lane >> 3) & 1) * 16;
#pragma unroll
        for (int p = 0; p < 2; ++p) {
            uint32_t bf[4];
            ldsm4(bf, sVb + vt_off(p * 16 + nrB, kbv));
            mma16816(oacc[2 * p],     pa[ks], bf);
            mma16816(oacc[2 * p + 1], pa[ks], bf + 2);
        }
    }

    if (r0 < NTOK) {
        __half* o = g_AOh + ((size_t)bw * NTOK + r0) * DIM_ + h * HD_;
#pragma unroll
        for (int f = 0; f < 4; ++f) {
            const int d = f * 8 + tg * 2;
            *(__half2*)(o + d) =
                __floats2half2_rn(oacc[f][0] * inv0, oacc[f][1] * inv0);
        }
    }
    if (r1 < NTOK) {
        __half* o = g_AOh + ((size_t)bw * NTOK + r1) * DIM_ + h * HD_;
#pragma unroll
        for (int f = 0; f < 4; ++f) {
            const int d = f * 8 + tg * 2;
            *(__half2*)(o + d) =
                __floats2half2_rn(oacc[f][2] * inv1, oacc[f][3] * inv1);
        }
    }
}

// ---------------------------------------------------------------------------
extern "C" void kernel_launch(void* const* d_in, const int* in_sizes, int n_in,
                              void* d_out, int out_size) {
    const float* x      = (const float*)d_in[0];
    const float* qkv_w  = (const float*)d_in[1];
    const float* qkv_b  = (const float*)d_in[2];
    const float* proj_w = (const float*)d_in[3];
    const float* proj_b = (const float*)d_in[4];
    const float* table  = (const float*)d_in[5];
    float* out = (float*)d_out;

    cudaFuncSetAttribute(gemm_h<0>, cudaFuncAttributeMaxDynamicSharedMemorySize, GSMEM);
    cudaFuncSetAttribute(gemm_h<1>, cudaFuncAttributeMaxDynamicSharedMemorySize, GSMEM);

    const int n4 = N4X + N4W + N4P;
    cvt_all<<<(n4 + 255) / 256, 256>>>((const float4*)x, (const float4*)qkv_w,
                                       (const float4*)proj_w);

    gemm_h<0><<<dim3((3 * DIM_) / BN, M_ / BM), 256, GSMEM>>>(qkv_b, nullptr);

    attn_tc<<<BW_ * NH_, 128>>>(table);

    gemm_h<1><<<dim3(DIM_ / BN, M_ / BM), 256, GSMEM>>>(proj_b, out);
}

// round 11
// speedup vs baseline: 1.1952x; 1.0293x over previous
#include <cuda_runtime.h>
#include <cuda_fp16.h>
#include <cstdint>

// ---------------------------------------------------------------------------
// Problem constants
// ---------------------------------------------------------------------------
#define BW_   2048
#define NTOK  49
#define NH_   12
#define HD_   32
#define DIM_  384
#define M_    (BW_ * NTOK)   // 100352
#define K_    DIM_

// fp16 scratch (device globals; allocation in kernel_launch is forbidden)
__device__ __align__(16) __half g_xh[M_ * DIM_];
__device__ __align__(16) __half g_wh[4 * DIM_ * DIM_];   // qkv_w then proj_w
__device__ __align__(16) __half g_Qh[BW_ * NH_ * NTOK * HD_];
__device__ __align__(16) __half g_Kh[BW_ * NH_ * NTOK * HD_];
__device__ __align__(16) __half g_Vh[BW_ * NH_ * NTOK * HD_];
__device__ __align__(16) __half g_AOh[M_ * DIM_];

// ---------------------------------------------------------------------------
// helpers
// ---------------------------------------------------------------------------
__device__ __forceinline__ uint32_t smem_u32(const void* p) {
    uint32_t a;
    asm("{ .reg .u64 t; cvta.to.shared.u64 t, %1; cvt.u32.u64 %0, t; }"
        : "=r"(a) : "l"(p));
    return a;
}

// 64B-row swizzle (rows of 32 fp16): conflict-free ldsm + 16B stores
__device__ __forceinline__ uint32_t sw_off(int row, int kb) {
    return (uint32_t)(row * 64 + (kb ^ (((row >> 1) & 3) << 4)));
}

__device__ __forceinline__ void ldsm4(uint32_t* r, uint32_t a) {
    asm volatile("ldmatrix.sync.aligned.m8n8.x4.shared.b16 {%0,%1,%2,%3}, [%4];"
                 : "=r"(r[0]), "=r"(r[1]), "=r"(r[2]), "=r"(r[3]) : "r"(a));
}

__device__ __forceinline__ void ldsm4t(uint32_t* r, uint32_t a) {
    asm volatile("ldmatrix.sync.aligned.m8n8.x4.trans.shared.b16 {%0,%1,%2,%3}, [%4];"
                 : "=r"(r[0]), "=r"(r[1]), "=r"(r[2]), "=r"(r[3]) : "r"(a));
}

__device__ __forceinline__ void mma16816(float* c, const uint32_t* a, const uint32_t* b) {
    asm volatile(
        "mma.sync.aligned.m16n8k16.row.col.f32.f16.f16.f32 "
        "{%0,%1,%2,%3}, {%4,%5,%6,%7}, {%8,%9}, {%0,%1,%2,%3};"
        : "+f"(c[0]), "+f"(c[1]), "+f"(c[2]), "+f"(c[3])
        : "r"(a[0]), "r"(a[1]), "r"(a[2]), "r"(a[3]), "r"(b[0]), "r"(b[1]));
}

__device__ __forceinline__ void cp16(uint32_t dst, const void* src) {
    asm volatile("cp.async.cg.shared.global [%0], [%1], 16;" :: "r"(dst), "l"(src));
}
#define CP_COMMIT() asm volatile("cp.async.commit_group;")
#define CP_WAIT(n)  asm volatile("cp.async.wait_group %0;" :: "n"(n))

__device__ __forceinline__ uint32_t h2u(__half2 h) { return *(uint32_t*)&h; }

// ---------------------------------------------------------------------------
// fp32 -> fp16 convert, all three tensors in one launch
// ---------------------------------------------------------------------------
#define N4X ((M_ * DIM_) / 4)
#define N4W ((3 * DIM_ * DIM_) / 4)
#define N4P ((DIM_ * DIM_) / 4)

__global__ void cvt_all(const float4* __restrict__ x,
                        const float4* __restrict__ qw,
                        const float4* __restrict__ pw) {
    int i = blockIdx.x * blockDim.x + threadIdx.x;
    const float4* src;
    __half* dst;
    int j;
    if (i < N4X)                 { src = x;  dst = g_xh;                   j = i; }
    else if (i < N4X + N4W)      { src = qw; dst = g_wh;                   j = i - N4X; }
    else if (i < N4X + N4W + N4P){ src = pw; dst = g_wh + 3 * DIM_ * DIM_; j = i - N4X - N4W; }
    else return;
    float4 f = src[j];
    uint2 u;
    u.x = h2u(__floats2half2_rn(f.x, f.y));
    u.y = h2u(__floats2half2_rn(f.z, f.w));
    *(uint2*)(dst + (size_t)j * 4) = u;
}

// ---------------------------------------------------------------------------
// fp16 GEMM (f32 acc): identical to round-10 best (518.6us config)
// CTA 128x128x32, 8 warps (4m x 2n), warp tile 32x64, 5-stage cp.async.
// ---------------------------------------------------------------------------
#define BM 128
#define BN 128
#define BK 32
#define KT (K_ / BK)            // 12
#define STAGES 5
#define A_ST (BM * BK * 2)      // 8192 B
#define B_ST (BN * BK * 2)      // 8192 B
#define STG_ (A_ST + B_ST)      // 16384 B
#define GSMEM (STAGES * STG_)   // 81920 B

template <int MODE>
__global__ __launch_bounds__(256, 2)
void gemm_h(const float* __restrict__ bias, float* __restrict__ out) {
    extern __shared__ __align__(16) uint8_t smem[];

    const __half* Ah = (MODE == 0) ? g_xh : g_AOh;
    const __half* Bh = (MODE == 0) ? g_wh : g_wh + 3 * DIM_ * DIM_;

    const int tid  = threadIdx.x;
    const int lane = tid & 31;
    const int wid  = tid >> 5;
    const int wm   = wid & 3;
    const int wn   = wid >> 2;
    const int bm   = blockIdx.y * BM;
    const int bn   = blockIdx.x * BN;

    const int lrow = tid >> 2;
    const int lc   = tid & 3;
    const __half* Asrc = Ah + (size_t)(bm + lrow) * K_ + lc * 8;
    const __half* Bsrc = Bh + (size_t)(bn + lrow) * K_ + lc * 8;
    const uint32_t sw0 = sw_off(lrow, lc * 16);
    const uint32_t sw1 = sw_off(lrow + 64, lc * 16);

    const uint32_t sb = smem_u32(smem);

    const int arow = wm * 32 + (lane & 15);
    const uint32_t akb = ((lane >> 4) & 1) * 16;
    const uint32_t aoff0 = sw_off(arow, akb);
    const uint32_t aoff1 = sw_off(arow + 16, akb);
    const int nrB = (lane & 7) + ((lane >> 4) & 1) * 8;
    const uint32_t bkb = ((lane >> 3) & 1) * 16;
    uint32_t boff[4];
#pragma unroll
    for (int p = 0; p < 4; ++p) boff[p] = sw_off(wn * 64 + p * 16 + nrB, bkb);

    float acc[2][8][4];
#pragma unroll
    for (int mf = 0; mf < 2; ++mf)
#pragma unroll
        for (int f = 0; f < 8; ++f)
#pragma unroll
            for (int e = 0; e < 4; ++e) acc[mf][f][e] = 0.f;

    auto issue = [&](int kt) {
        const uint32_t ab = sb + (kt % STAGES) * STG_;
        const uint32_t bb = ab + A_ST;
        const __half* as = Asrc + kt * BK;
        const __half* bs = Bsrc + kt * BK;
        cp16(ab + sw0, as);
        cp16(ab + sw1, as + (size_t)64 * K_);
        cp16(bb + sw0, bs);
        cp16(bb + sw1, bs + (size_t)64 * K_);
        CP_COMMIT();
    };

    issue(0); issue(1); issue(2); issue(3);

#pragma unroll
    for (int kt = 0; kt < KT; ++kt) {
        if (kt < KT - 3)      { CP_WAIT(3); }
        else if (kt == KT - 3){ CP_WAIT(2); }
        else if (kt == KT - 2){ CP_WAIT(1); }
        else                  { CP_WAIT(0); }
        __syncthreads();
        if (kt + 4 < KT) issue(kt + 4);

        const uint32_t aB = sb + (kt % STAGES) * STG_;
        const uint32_t bB = aB + A_ST;
#pragma unroll
        for (int ks = 0; ks < 2; ++ks) {
            const uint32_t kx = (uint32_t)ks << 5;
            uint32_t af0[4], af1[4];
            ldsm4(af0, aB + (aoff0 ^ kx));
            ldsm4(af1, aB + (aoff1 ^ kx));
#pragma unroll
            for (int p = 0; p < 4; ++p) {
                uint32_t bf[4];
                ldsm4(bf, bB + (boff[p] ^ kx));
                mma16816(acc[0][2 * p],     af0, bf);
                mma16816(acc[0][2 * p + 1], af0, bf + 2);
                mma16816(acc[1][2 * p],     af1, bf);
                mma16816(acc[1][2 * p + 1], af1, bf + 2);
            }
        }
    }

    const int gr = lane >> 2, tg = lane & 3;

    if (MODE == 0) {
        const int which = bn / DIM_;
        const float scl = (which == 0) ? 0.17677669529663687f : 1.0f;
        __half* dst = (which == 0) ? g_Qh : (which == 1) ? g_Kh : g_Vh;
#pragma unroll
        for (int mf = 0; mf < 2; ++mf) {
#pragma unroll
            for (int e = 0; e < 2; ++e) {
                const int row = bm + wm * 32 + mf * 16 + gr + e * 8;
                const int bwin = row / NTOK;
                const int t = row - bwin * NTOK;
#pragma unroll
                for (int f = 0; f < 8; ++f) {
                    const int n = bn + wn * 64 + f * 8 + tg * 2;
                    const int hh = (n - which * DIM_) >> 5;
                    const int cl = n & 31;
                    float v0 = (acc[mf][f][e * 2 + 0] + bias[n + 0]) * scl;
                    float v1 = (acc[mf][f][e * 2 + 1] + bias[n + 1]) * scl;
                    *(__half2*)(dst + ((size_t)(bwin * NH_ + hh) * NTOK + t) * HD_ + cl) =
                        __floats2half2_rn(v0, v1);
                }
            }
        }
    } else {
#pragma unroll
        for (int mf = 0; mf < 2; ++mf) {
#pragma unroll
            for (int e = 0; e < 2; ++e) {
                const int row = bm + wm * 32 + mf * 16 + gr + e * 8;
#pragma unroll
                for (int f = 0; f < 8; ++f) {
                    const int n = bn + wn * 64 + f * 8 + tg * 2;
                    float2 w;
                    w.x = acc[mf][f][e * 2 + 0] + bias[n + 0];
                    w.y = acc[mf][f][e * 2 + 1] + bias[n + 1];
                    *(float2*)(out + (size_t)row * DIM_ + n) = w;
                }
            }
        }
    }
}

// ---------------------------------------------------------------------------
// Tensorized window attention: 256-thr CTA = 2 (window,head) pairs.
// Q/K/V cp.async'd into 64-row swizzled tiles; PV uses ldmatrix.trans on
// row-major V (no transpose scatter). V pad rows zeroed (P*garbage safety).
// ---------------------------------------------------------------------------
#define APAIRS 2

__global__ __launch_bounds__(256)
void attn_tc(const float* __restrict__ table) {
    __shared__ __align__(16) __half sQ[APAIRS][64 * 32];
    __shared__ __align__(16) __half sK[APAIRS][64 * 32];
    __shared__ __align__(16) __half sV[APAIRS][64 * 32];
    __shared__ float sbias[APAIRS][169];

    const int tid  = threadIdx.x;
    const int hp   = tid >> 7;        // half-CTA = pair slot
    const int wtid = tid & 127;
    const int lane = tid & 31;
    const int w    = (wtid >> 5);     // warp within half (0..3)

    const int pair = blockIdx.x * APAIRS + hp;
    const int bw   = pair / NH_;
    const int h    = pair - bw * NH_;

    const __half* qg = g_Qh + (size_t)pair * NTOK * HD_;
    const __half* kg = g_Kh + (size_t)pair * NTOK * HD_;
    const __half* vg = g_Vh + (size_t)pair * NTOK * HD_;
    const uint32_t sQb = smem_u32(sQ[hp]);
    const uint32_t sKb = smem_u32(sK[hp]);
    const uint32_t sVb = smem_u32(sV[hp]);

    // zero V pad rows 49..63 (15 rows x 4 chunks = 60) — threads 0..59
    if (wtid < 60) {
        const int row = 49 + (wtid >> 2);
        *(uint4*)((char*)sV[hp] + sw_off(row, (wtid & 3) * 16)) = make_uint4(0, 0, 0, 0);
    }
    // cp.async Q, K, V (49 rows x 4 16B-chunks each)
    for (int i = wtid; i < 196; i += 128) {
        const int row = i >> 2, cb = (i & 3) * 16;
        const uint32_t so = sw_off(row, cb);
        const size_t go = (size_t)row * HD_ + (i & 3) * 8;
        cp16(sQb + so, qg + go);
        cp16(sKb + so, kg + go);
        cp16(sVb + so, vg + go);
    }
    CP_COMMIT();
    for (int i = wtid; i < 169; i += 128) sbias[hp][i] = table[i * NH_ + h];
    CP_WAIT(0);
    __syncthreads();

    const int gr = lane >> 2, tg = lane & 3;

    // ---- S = Q K^T (warp w: rows w*16..+15, cols 0..63)
    float sacc[8][4];
#pragma unroll
    for (int f = 0; f < 8; ++f)
#pragma unroll
        for (int e = 0; e < 4; ++e) sacc[f][e] = 0.f;

    const uint32_t aoff = sw_off(w * 16 + (lane & 15), ((lane >> 4) & 1) * 16);
    const int nrB = (lane & 7) + ((lane >> 4) & 1) * 8;
    const uint32_t bkb = ((lane >> 3) & 1) * 16;
#pragma unroll
    for (int ks = 0; ks < 2; ++ks) {
        const uint32_t kx = ks * 32;
        uint32_t af[4];
        ldsm4(af, sQb + (aoff ^ kx));
#pragma unroll
        for (int p = 0; p < 4; ++p) {
            uint32_t bf[4];
            ldsm4(bf, sKb + (sw_off(p * 16 + nrB, bkb) ^ kx));
            mma16816(sacc[2 * p],     af, bf);
            mma16816(sacc[2 * p + 1], af, bf + 2);
        }
    }

    // ---- bias + mask + softmax (rows r0 = w*16+gr, r1 = r0+8)
    const int r0 = w * 16 + gr, r1 = r0 + 8;
    const int r0d = r0 / 7, r0m = r0 - r0d * 7;
    const int r1d = r1 / 7, r1m = r1 - r1d * 7;
    float mx0 = -1e30f, mx1 = -1e30f;
#pragma unroll
    for (int f = 0; f < 8; ++f) {
#pragma unroll
        for (int c = 0; c < 2; ++c) {
            const int j = f * 8 + tg * 2 + c;
            const int jd = j / 7, jm = j - jd * 7;
            const bool jv = (j < NTOK);
            float s0 = -1e30f, s1 = -1e30f;
            if (jv) {
                float b0 = (r0 < NTOK) ? sbias[hp][(r0d - jd + 6) * 13 + (r0m - jm + 6)] : 0.f;
                float b1 = (r1 < NTOK) ? sbias[hp][(r1d - jd + 6) * 13 + (r1m - jm + 6)] : 0.f;
                s0 = sacc[f][c]     + b0;
                s1 = sacc[f][c + 2] + b1;
            }
            sacc[f][c]     = s0;
            sacc[f][c + 2] = s1;
            mx0 = fmaxf(mx0, s0);
            mx1 = fmaxf(mx1, s1);
        }
    }
    mx0 = fmaxf(mx0, __shfl_xor_sync(0xffffffffu, mx0, 1));
    mx0 = fmaxf(mx0, __shfl_xor_sync(0xffffffffu, mx0, 2));
    mx1 = fmaxf(mx1, __shfl_xor_sync(0xffffffffu, mx1, 1));
    mx1 = fmaxf(mx1, __shfl_xor_sync(0xffffffffu, mx1, 2));

    float sum0 = 0.f, sum1 = 0.f;
#pragma unroll
    for (int f = 0; f < 8; ++f) {
        float e0 = __expf(sacc[f][0] - mx0);
        float e1 = __expf(sacc[f][1] - mx0);
        float e2 = __expf(sacc[f][2] - mx1);
        float e3 = __expf(sacc[f][3] - mx1);
        sacc[f][0] = e0; sacc[f][1] = e1; sacc[f][2] = e2; sacc[f][3] = e3;
        sum0 += e0 + e1;
        sum1 += e2 + e3;
    }
    sum0 += __shfl_xor_sync(0xffffffffu, sum0, 1);
    sum0 += __shfl_xor_sync(0xffffffffu, sum0, 2);
    sum1 += __shfl_xor_sync(0xffffffffu, sum1, 1);
    sum1 += __shfl_xor_sync(0xffffffffu, sum1, 2);
    const float inv0 = __frcp_rn(sum0);
    const float inv1 = __frcp_rn(sum1);

    // ---- P -> A fragments (acc->A identity)
    uint32_t pa[4][4];
#pragma unroll
    for (int ks = 0; ks < 4; ++ks) {
        pa[ks][0] = h2u(__floats2half2_rn(sacc[2 * ks][0],     sacc[2 * ks][1]));
        pa[ks][1] = h2u(__floats2half2_rn(sacc[2 * ks][2],     sacc[2 * ks][3]));
        pa[ks][2] = h2u(__floats2half2_rn(sacc[2 * ks + 1][0], sacc[2 * ks + 1][1]));
        pa[ks][3] = h2u(__floats2half2_rn(sacc[2 * ks + 1][2], sacc[2 * ks + 1][3]));
    }

    // ---- O = P V via ldmatrix.trans on row-major V
    // lane -> (row-in-16, col-half): rows ks*16 + {0-7,8-15}, byte col p*32 + {0,16}
    const int vrl   = ((lane >> 3) & 1) * 8 + (lane & 7);
    const int vcsel = (lane >> 4) * 16;

    float oacc[4][4];
#pragma unroll
    for (int f = 0; f < 4; ++f)
#pragma unroll
        for (int e = 0; e < 4; ++e) oacc[f][e] = 0.f;

#pragma unroll
    for (int ks = 0; ks < 4; ++ks) {
#pragma unroll
        for (int p = 0; p < 2; ++p) {
            uint32_t bf[4];
            ldsm4t(bf, sVb + sw_off(ks * 16 + vrl, p * 32 + vcsel));
            mma16816(oacc[2 * p],     pa[ks], bf);
            mma16816(oacc[2 * p + 1], pa[ks], bf + 2);
        }
    }

    if (r0 < NTOK) {
        __half* o = g_AOh + ((size_t)bw * NTOK + r0) * DIM_ + h * HD_;
#pragma unroll
        for (int f = 0; f < 4; ++f) {
            const int d = f * 8 + tg * 2;
            *(__half2*)(o + d) =
                __floats2half2_rn(oacc[f][0] * inv0, oacc[f][1] * inv0);
        }
    }
    if (r1 < NTOK) {
        __half* o = g_AOh + ((size_t)bw * NTOK + r1) * DIM_ + h * HD_;
#pragma unroll
        for (int f = 0; f < 4; ++f) {
            const int d = f * 8 + tg * 2;
            *(__half2*)(o + d) =
                __floats2half2_rn(oacc[f][2] * inv1, oacc[f][3] * inv1);
        }
    }
}

// ---------------------------------------------------------------------------
extern "C" void kernel_launch(void* const* d_in, const int* in_sizes, int n_in,
                              void* d_out, int out_size) {
    const float* x      = (const float*)d_in[0];
    const float* qkv_w  = (const float*)d_in[1];
    const float* qkv_b  = (const float*)d_in[2];
    const float* proj_w = (const float*)d_in[3];
    const float* proj_b = (const float*)d_in[4];
    const float* table  = (const float*)d_in[5];
    float* out = (float*)d_out;

    cudaFuncSetAttribute(gemm_h<0>, cudaFuncAttributeMaxDynamicSharedMemorySize, GSMEM);
    cudaFuncSetAttribute(gemm_h<1>, cudaFuncAttributeMaxDynamicSharedMemorySize, GSMEM);

    const int n4 = N4X + N4W + N4P;
    cvt_all<<<(n4 + 255) / 256, 256>>>((const float4*)x, (const float4*)qkv_w,
                                       (const float4*)proj_w);

    gemm_h<0><<<dim3((3 * DIM_) / BN, M_ / BM), 256, GSMEM>>>(qkv_b, nullptr);

    attn_tc<<<(BW_ * NH_) / APAIRS, 256>>>(table);

    gemm_h<1><<<dim3(DIM_ / BN, M_ / BM), 256, GSMEM>>>(proj_b, out);
}